// round 8
// baseline (speedup 1.0000x reference)
#include <cuda_runtime.h>
#include <cstdint>
#include <cfloat>

// Problem constants
#define NF    1024
#define BATCH 1024
#define HW    64
#define PIX   (HW * HW)     // 4096
#define PAD   3
#define PW    70            // padded side
#define PPIX  (PW * PW)     // 4900
#define FHALF 512           // filters per block
#define FITER 4             // 512 / 128 threads

// ---------------------------------------------------------------------------
// Packed f32x2 helpers (Blackwell packed-FP32 pipe: 2x FFMA throughput)
// ---------------------------------------------------------------------------
__device__ __forceinline__ unsigned long long ffma2(unsigned long long a,
                                                    unsigned long long b,
                                                    unsigned long long c) {
    unsigned long long d;
    asm("fma.rn.f32x2 %0, %1, %2, %3;" : "=l"(d) : "l"(a), "l"(b), "l"(c));
    return d;
}
__device__ __forceinline__ unsigned long long fmul2(unsigned long long a,
                                                    unsigned long long b) {
    unsigned long long d;
    asm("mul.rn.f32x2 %0, %1, %2;" : "=l"(d) : "l"(a), "l"(b));
    return d;
}
__device__ __forceinline__ unsigned long long pack2(float x, float y) {
    unsigned long long r;
    asm("mov.b64 %0, {%1, %2};" : "=l"(r) : "f"(x), "f"(y));
    return r;
}
__device__ __forceinline__ float2 unpack2(unsigned long long v) {
    float2 r;
    asm("mov.b64 {%0, %1}, %2;" : "=f"(r.x), "=f"(r.y) : "l"(v));
    return r;
}

// ---------------------------------------------------------------------------
// Fused kernel: block = (batch-pair, filter-half).
//  1. Build zero-padded 70x70x2 image slab in SMEM from X (coalesced).
//  2. For each of 512 filters: 5x5 conv on the 6x6 outputs the pool reads
//     (window rows via LDS.64 immediate-offset), bias + 3x3/3 maxpool, store.
// All math is packed f32x2 (lane .x = batch b0, .y = b0+1).
// ---------------------------------------------------------------------------
__global__ void __launch_bounds__(128, 3) filters_fused_kernel(
    const float* __restrict__ X,      // [B, 4096]
    const float* __restrict__ W,      // [NF, 25]
    const float* __restrict__ bias,   // [NF]
    const int*   __restrict__ pos,    // [NF, 2]
    float*       __restrict__ out)    // [B, NF*4]
{
    __shared__ float slab[PPIX * 2];  // [padded_pixel][2 batches] = 39.2 KB

    const int tid = threadIdx.x;
    const int b0  = blockIdx.x * 2;        // batch pair
    const int fh  = blockIdx.y;            // filter half (0/1)

    // ---- Phase 1: zero slab, then fill interior from X (coalesced) ----
    float4* s4 = (float4*)slab;
#pragma unroll 1
    for (int i = tid; i < (PPIX * 2) / 4; i += 128)
        s4[i] = make_float4(0.f, 0.f, 0.f, 0.f);
    __syncthreads();

#pragma unroll
    for (int q = 0; q < 2; q++) {
        const float4* src = (const float4*)(X + (size_t)(b0 + q) * PIX);
#pragma unroll 1
        for (int i = tid; i < PIX / 4; i += 128) {
            const float4 v = src[i];
            const int p = i * 4;
            const int y = p >> 6, x = p & 63;   // rows are 64 wide, 4 | 64
            const int s = ((y + PAD) * PW + (x + PAD)) * 2 + q;
            slab[s]     = v.x;
            slab[s + 2] = v.y;
            slab[s + 4] = v.z;
            slab[s + 6] = v.w;
        }
    }
    __syncthreads();

    // ---- Phase 2: filter sweep (slab is read-only; no more barriers) ----
    const unsigned long long* slab2 = (const unsigned long long*)slab;

#pragma unroll 1
    for (int it = 0; it < FITER; it++) {
        const int f  = fh * FHALF + it * 128 + tid;
        const int pi = __ldg(&pos[2 * f]);
        const int pj = __ldg(&pos[2 * f + 1]);
        const unsigned long long* win = slab2 + (pi * PW + pj);

        // Broadcast-pack 25 weights (L1-resident across blocks).
        unsigned long long wp[25];
#pragma unroll
        for (int k = 0; k < 25; k++) {
            const float w = __ldg(&W[f * 25 + k]);
            wp[k] = pack2(w, w);
        }

        // 6x6 packed accumulators; first touch (ky==0, kx==0) is a MUL so
        // no explicit zero-init is needed.
        unsigned long long acc[36];

#pragma unroll
        for (int r = 0; r < 10; r++) {
            unsigned long long row[10];
#pragma unroll
            for (int c = 0; c < 10; c++)
                row[c] = win[r * PW + c];     // LDS.64, immediate offset

#pragma unroll
            for (int oy = 0; oy < 6; oy++) {
                const int ky = r - oy;
                if (ky < 0 || ky > 4) continue;   // compile-time pruned
#pragma unroll
                for (int ox = 0; ox < 6; ox++) {
#pragma unroll
                    for (int kx = 0; kx < 5; kx++) {
                        if (ky == 0 && kx == 0)
                            acc[oy * 6 + ox] = fmul2(row[ox], wp[0]);
                        else
                            acc[oy * 6 + ox] = ffma2(row[ox + kx],
                                                     wp[ky * 5 + kx],
                                                     acc[oy * 6 + ox]);
                    }
                }
            }
        }

        // ---- bias + 3x3 stride-3 maxpool -> 2x2, one float4 per batch ----
        const float bv = __ldg(&bias[f]);
        float m0[4], m1[4];
#pragma unroll
        for (int py = 0; py < 2; py++) {
#pragma unroll
            for (int px = 0; px < 2; px++) {
                float a0 = -FLT_MAX, a1 = -FLT_MAX;
#pragma unroll
                for (int dy = 0; dy < 3; dy++) {
#pragma unroll
                    for (int dx = 0; dx < 3; dx++) {
                        const float2 v =
                            unpack2(acc[(3 * py + dy) * 6 + (3 * px + dx)]);
                        a0 = fmaxf(a0, v.x);
                        a1 = fmaxf(a1, v.y);
                    }
                }
                m0[py * 2 + px] = a0 + bv;
                m1[py * 2 + px] = a1 + bv;
            }
        }

        // out[b, f*4 + j]; lanes = consecutive f -> contiguous 512B stores.
        float4* o0 = (float4*)(out + (size_t)b0 * (NF * 4) + f * 4);
        float4* o1 = (float4*)(out + (size_t)(b0 + 1) * (NF * 4) + f * 4);
        *o0 = make_float4(m0[0], m0[1], m0[2], m0[3]);
        *o1 = make_float4(m1[0], m1[1], m1[2], m1[3]);
    }
}

// ---------------------------------------------------------------------------
// kernel_launch: ONE fused kernel. Graph-capturable, allocation-free.
// ---------------------------------------------------------------------------
extern "C" void kernel_launch(void* const* d_in, const int* in_sizes, int n_in,
                              void* d_out, int out_size) {
    (void)in_sizes; (void)n_in; (void)out_size;
    const float* X    = (const float*)d_in[0];
    const float* W    = (const float*)d_in[1];
    const float* bias = (const float*)d_in[2];
    const int*   pos  = (const int*)d_in[3];
    float*       out  = (float*)d_out;

    dim3 grid(BATCH / 2, 2);     // (512 pairs, 2 filter-halves) = 1024 blocks
    filters_fused_kernel<<<grid, 128>>>(X, W, bias, pos, out);
}

// round 9
// speedup vs baseline: 1.0050x; 1.0050x over previous
#include <cuda_runtime.h>
#include <cstdint>
#include <cfloat>

// Problem constants
#define NF    1024
#define BATCH 1024
#define HW    64
#define PIX   (HW * HW)     // 4096
#define PAD   3
#define PW    70            // padded side
#define PPIX  (PW * PW)     // 4900
#define NCHUNK 4            // batch chunks of 256
#define NITEMS (NF * NCHUNK)
#define NBLK  444           // 148 SMs * 3 resident blocks -> single wave

// 20 MB scratch: zero-PADDED image transposed to [padded_pixel][batch].
// __device__ globals are zero-initialized at module load; the transpose only
// writes interior pixels, so the 3-wide border is permanently zero -> the conv
// loop needs no bounds checks and no border-zero kernel.
__device__ float g_xt[(size_t)PPIX * BATCH];

// Filter processing order, counting-sorted by 6x6 position bucket so that
// consecutive items have overlapping windows (L1 reuse within a block).
__device__ int g_order[NF];

// ---------------------------------------------------------------------------
// Kernel 1: bucket counting-sort of filters by window position (1 block).
// Order within a bucket is atomic-race dependent, but every filter appears
// exactly once and each filter's output is computed identically -> d_out is
// deterministic.
// ---------------------------------------------------------------------------
__global__ void sort_kernel(const int* __restrict__ pos) {
    __shared__ int cnt[128];
    __shared__ int off[128];
    const int t = threadIdx.x;          // 1024 threads = NF
    if (t < 128) cnt[t] = 0;
    __syncthreads();
    const int pi = pos[2 * t], pj = pos[2 * t + 1];   // in [0, 60]
    const int key = (pi / 6) * 11 + (pj / 6);         // 11x11 = 121 buckets
    atomicAdd(&cnt[key], 1);
    __syncthreads();
    if (t == 0) {
        int s = 0;
        for (int i = 0; i < 121; i++) { off[i] = s; s += cnt[i]; }
    }
    __syncthreads();
    const int r = atomicAdd(&off[key], 1);
    g_order[r] = t;
}

// ---------------------------------------------------------------------------
// Kernel 2: transpose X [B, 4096] -> interior of g_xt [4900, B]
// ---------------------------------------------------------------------------
__global__ void xt_transpose_kernel(const float* __restrict__ X) {
    __shared__ float tile[32][33];
    const int p0 = blockIdx.x * 32;
    const int b0 = blockIdx.y * 32;
    const int tx = threadIdx.x;
    const int ty = threadIdx.y;
#pragma unroll
    for (int k = 0; k < 32; k += 8)
        tile[ty + k][tx] = X[(size_t)(b0 + ty + k) * PIX + (p0 + tx)];
    __syncthreads();
#pragma unroll
    for (int k = 0; k < 32; k += 8) {
        const int p = p0 + ty + k;
        const int y = p >> 6, x = p & 63;
        g_xt[(size_t)((y + PAD) * PW + (x + PAD)) * BATCH + (b0 + tx)] =
            tile[tx][ty + k];
    }
}

// ---------------------------------------------------------------------------
// Packed f32x2 helpers (Blackwell packed-FP32 pipe: 2x FFMA throughput)
// ---------------------------------------------------------------------------
__device__ __forceinline__ unsigned long long ffma2(unsigned long long a,
                                                    unsigned long long b,
                                                    unsigned long long c) {
    unsigned long long d;
    asm("fma.rn.f32x2 %0, %1, %2, %3;" : "=l"(d) : "l"(a), "l"(b), "l"(c));
    return d;
}
__device__ __forceinline__ unsigned long long fmul2(unsigned long long a,
                                                    unsigned long long b) {
    unsigned long long d;
    asm("mul.rn.f32x2 %0, %1, %2;" : "=l"(d) : "l"(a), "l"(b));
    return d;
}
__device__ __forceinline__ unsigned long long pack2(float x, float y) {
    unsigned long long r;
    asm("mov.b64 %0, {%1, %2};" : "=l"(r) : "f"(x), "f"(y));
    return r;
}
__device__ __forceinline__ float2 unpack2(unsigned long long v) {
    float2 r;
    asm("mov.b64 {%0, %1}, %2;" : "=f"(r.x), "=f"(r.y) : "l"(v));
    return r;
}

// ---------------------------------------------------------------------------
// Kernel 3: persistent conv blocks. Each of the 444 blocks (one full wave at
// 3 blocks/SM) processes a contiguous run of sorted (chunk, filter) items.
// Within a block: lanes = batches (conflict-free, coalesced 256B row loads),
// one filter at a time; consecutive filters share most of their window in L1.
// Per item: 5x5 conv on the 6x6 outputs the pool reads + bias + 3x3/3 maxpool.
// ---------------------------------------------------------------------------
__global__ void __launch_bounds__(128, 3) filters_conv_kernel(
    const float* __restrict__ W,      // [NF, 25]
    const float* __restrict__ bias,   // [NF]
    const int*   __restrict__ pos,    // [NF, 2]
    float*       __restrict__ out)    // [B, NF*4]
{
    const int start = (int)(((long long)blockIdx.x * NITEMS) / NBLK);
    const int end   = (int)(((long long)(blockIdx.x + 1) * NITEMS) / NBLK);

#pragma unroll 1
    for (int item = start; item < end; item++) {
        const int f     = g_order[item & (NF - 1)];
        const int chunk = item >> 10;                    // 0..3
        const int b     = chunk * 256 + threadIdx.x * 2; // even -> 8B aligned
        const int pi = __ldg(&pos[2 * f]);
        const int pj = __ldg(&pos[2 * f + 1]);

        // Single base pointer; every load uses a compile-time byte offset.
        const char* p0 = (const char*)g_xt +
                         ((size_t)(pi * PW + pj) * BATCH + b) * sizeof(float);

        // Broadcast-pack the 25 weights into (w, w) register pairs.
        unsigned long long wp[25];
#pragma unroll
        for (int k = 0; k < 25; k++) {
            const float w = __ldg(&W[f * 25 + k]);
            wp[k] = pack2(w, w);
        }

        // 6x6 packed accumulators; first touch (ky==0,kx==0) is a MUL.
        unsigned long long acc[36];

#pragma unroll
        for (int r = 0; r < 10; r++) {
            unsigned long long row[10];
#pragma unroll
            for (int c = 0; c < 10; c++)
                row[c] = *(const unsigned long long*)(
                    p0 + (size_t)((r * PW + c) * BATCH) * sizeof(float));

#pragma unroll
            for (int oy = 0; oy < 6; oy++) {
                const int ky = r - oy;
                if (ky < 0 || ky > 4) continue;   // compile-time pruned
#pragma unroll
                for (int ox = 0; ox < 6; ox++) {
#pragma unroll
                    for (int kx = 0; kx < 5; kx++) {
                        if (ky == 0 && kx == 0)
                            acc[oy * 6 + ox] = fmul2(row[ox], wp[0]);
                        else
                            acc[oy * 6 + ox] = ffma2(row[ox + kx],
                                                     wp[ky * 5 + kx],
                                                     acc[oy * 6 + ox]);
                    }
                }
            }
        }

        // bias + 3x3 stride-3 maxpool -> 2x2, one float4 per batch.
        const float bv = __ldg(&bias[f]);
        float m0[4], m1[4];
#pragma unroll
        for (int py = 0; py < 2; py++) {
#pragma unroll
            for (int px = 0; px < 2; px++) {
                float a0 = -FLT_MAX, a1 = -FLT_MAX;
#pragma unroll
                for (int dy = 0; dy < 3; dy++) {
#pragma unroll
                    for (int dx = 0; dx < 3; dx++) {
                        const float2 v =
                            unpack2(acc[(3 * py + dy) * 6 + (3 * px + dx)]);
                        a0 = fmaxf(a0, v.x);
                        a1 = fmaxf(a1, v.y);
                    }
                }
                m0[py * 2 + px] = a0 + bv;
                m1[py * 2 + px] = a1 + bv;
            }
        }

        float4* o0 = (float4*)(out + (size_t)b * (NF * 4) + f * 4);
        float4* o1 = (float4*)(out + (size_t)(b + 1) * (NF * 4) + f * 4);
        *o0 = make_float4(m0[0], m0[1], m0[2], m0[3]);
        *o1 = make_float4(m1[0], m1[1], m1[2], m1[3]);
    }
}

// ---------------------------------------------------------------------------
// kernel_launch: sort + transpose + persistent conv. Graph-capturable,
// allocation-free (scratch/order are __device__ globals; border of g_xt
// relies on guaranteed zero-initialization and is never written).
// ---------------------------------------------------------------------------
extern "C" void kernel_launch(void* const* d_in, const int* in_sizes, int n_in,
                              void* d_out, int out_size) {
    (void)in_sizes; (void)n_in; (void)out_size;
    const float* X    = (const float*)d_in[0];
    const float* W    = (const float*)d_in[1];
    const float* bias = (const float*)d_in[2];
    const int*   pos  = (const int*)d_in[3];
    float*       out  = (float*)d_out;

    sort_kernel<<<1, NF>>>(pos);

    dim3 tb(32, 8);
    dim3 tg(PIX / 32, BATCH / 32);         // (128, 32)
    xt_transpose_kernel<<<tg, tb>>>(X);

    filters_conv_kernel<<<NBLK, 128>>>(W, bias, pos, out);
}

// round 10
// speedup vs baseline: 1.0870x; 1.0817x over previous
#include <cuda_runtime.h>
#include <cuda_fp16.h>
#include <cstdint>
#include <cfloat>

// Problem constants
#define NF    1024
#define BATCH 1024
#define HW    64
#define PIX   (HW * HW)     // 4096
#define PAD   3
#define PW    70            // padded side
#define PPIX  (PW * PW)     // 4900

// 10 MB scratch: zero-PADDED image, fp16, transposed to [padded_pixel][batch].
// __device__ globals are zero-initialized at module load (fp16 zero == 0x0000)
// and the transpose never writes the 3-wide border, so the conv loop needs no
// bounds checks, no border kernel, and no per-load address math.
__device__ __half g_xh[(size_t)PPIX * BATCH];

// ---------------------------------------------------------------------------
// Kernel 1: transpose + fp32->fp16 convert.  X [B, 4096] -> g_xh interior.
// ---------------------------------------------------------------------------
__global__ void xt_transpose_kernel(const float* __restrict__ X) {
    __shared__ float tile[32][33];         // [batch_local][pixel_local]
    const int p0 = blockIdx.x * 32;        // pixel tile origin
    const int b0 = blockIdx.y * 32;        // batch tile origin
    const int tx = threadIdx.x;            // block (32, 8)
    const int ty = threadIdx.y;
#pragma unroll
    for (int k = 0; k < 32; k += 8)
        tile[ty + k][tx] = X[(size_t)(b0 + ty + k) * PIX + (p0 + tx)];
    __syncthreads();

    const int t  = ty * 32 + tx;           // 0..255
    const int bp = t & 15;                 // batch pair 0..15
    const int pr = t >> 4;                 // pixel row 0..15
#pragma unroll
    for (int k = 0; k < 32; k += 16) {
        const int p = p0 + pr + k;
        const int y = p >> 6, x = p & 63;
        const __half2 v = __floats2half2_rn(tile[2 * bp][pr + k],
                                            tile[2 * bp + 1][pr + k]);
        *(__half2*)(g_xh + (size_t)((y + PAD) * PW + (x + PAD)) * BATCH
                         + b0 + 2 * bp) = v;
    }
}

// ---------------------------------------------------------------------------
// Packed f32x2 helpers (Blackwell packed-FP32 pipe: 2x FFMA throughput)
// ---------------------------------------------------------------------------
__device__ __forceinline__ unsigned long long ffma2(unsigned long long a,
                                                    unsigned long long b,
                                                    unsigned long long c) {
    unsigned long long d;
    asm("fma.rn.f32x2 %0, %1, %2, %3;" : "=l"(d) : "l"(a), "l"(b), "l"(c));
    return d;
}
__device__ __forceinline__ unsigned long long fmul2(unsigned long long a,
                                                    unsigned long long b) {
    unsigned long long d;
    asm("mul.rn.f32x2 %0, %1, %2;" : "=l"(d) : "l"(a), "l"(b));
    return d;
}
__device__ __forceinline__ unsigned long long pack2(float x, float y) {
    unsigned long long r;
    asm("mov.b64 %0, {%1, %2};" : "=l"(r) : "f"(x), "f"(y));
    return r;
}
__device__ __forceinline__ float2 unpack2(unsigned long long v) {
    float2 r;
    asm("mov.b64 {%0, %1}, %2;" : "=f"(r.x), "=f"(r.y) : "l"(v));
    return r;
}

// ---------------------------------------------------------------------------
// Kernel 2: per (filter, batch-pair) fused 5x5 conv (only the 6x6 of the 7x7
// outputs the pool reads) + bias + 3x3/3 maxpool.  Each thread owns TWO
// adjacent batches: loads one LDG.32 (__half2) per window pixel with a
// compile-time immediate offset, converts once, then packed f32x2 FMAs.
// ---------------------------------------------------------------------------
__global__ void __launch_bounds__(128, 3) filters_conv_kernel(
    const float* __restrict__ W,      // [NF, 25]
    const float* __restrict__ bias,   // [NF]
    const int*   __restrict__ pos,    // [NF, 2]
    float*       __restrict__ out)    // [B, NF*4]
{
    const int f = blockIdx.x;
    const int b = blockIdx.y * 256 + threadIdx.x * 2;  // even -> 4B aligned
    const int pi = __ldg(&pos[2 * f]);
    const int pj = __ldg(&pos[2 * f + 1]);

    // Single base pointer; every load below uses a constant byte offset.
    const char* p0 = (const char*)g_xh +
                     ((size_t)(pi * PW + pj) * BATCH + b) * sizeof(__half);

    // Broadcast-pack the 25 fp32 weights into (w, w) register pairs.
    unsigned long long wp[25];
#pragma unroll
    for (int k = 0; k < 25; k++) {
        const float w = __ldg(&W[f * 25 + k]);
        wp[k] = pack2(w, w);
    }

    // 6x6 packed accumulators; first touch (ky==0,kx==0) is a MUL.
    unsigned long long acc[36];

    // Stream the 10 window rows of the zero-padded fp16 image.
#pragma unroll
    for (int r = 0; r < 10; r++) {
        unsigned long long row[10];
#pragma unroll
        for (int c = 0; c < 10; c++) {
            const __half2 h = *(const __half2*)(
                p0 + (size_t)((r * PW + c) * BATCH) * sizeof(__half));
            const float2 fv = __half22float2(h);
            row[c] = pack2(fv.x, fv.y);
        }

        // Row r feeds conv rows oy with ky = r - oy in [0,4].
#pragma unroll
        for (int oy = 0; oy < 6; oy++) {
            const int ky = r - oy;
            if (ky < 0 || ky > 4) continue;   // compile-time pruned
#pragma unroll
            for (int ox = 0; ox < 6; ox++) {
#pragma unroll
                for (int kx = 0; kx < 5; kx++) {
                    if (ky == 0 && kx == 0)
                        acc[oy * 6 + ox] = fmul2(row[ox], wp[0]);
                    else
                        acc[oy * 6 + ox] = ffma2(row[ox + kx],
                                                 wp[ky * 5 + kx],
                                                 acc[oy * 6 + ox]);
                }
            }
        }
    }

    // bias + 3x3 stride-3 maxpool -> 2x2, one float4 per batch.
    const float bv = __ldg(&bias[f]);
    float m0[4], m1[4];
#pragma unroll
    for (int py = 0; py < 2; py++) {
#pragma unroll
        for (int px = 0; px < 2; px++) {
            float a0 = -FLT_MAX, a1 = -FLT_MAX;
#pragma unroll
            for (int dy = 0; dy < 3; dy++) {
#pragma unroll
                for (int dx = 0; dx < 3; dx++) {
                    const float2 v =
                        unpack2(acc[(3 * py + dy) * 6 + (3 * px + dx)]);
                    a0 = fmaxf(a0, v.x);
                    a1 = fmaxf(a1, v.y);
                }
            }
            m0[py * 2 + px] = a0 + bv;
            m1[py * 2 + px] = a1 + bv;
        }
    }

    float4* o0 = (float4*)(out + (size_t)b * (NF * 4) + f * 4);
    float4* o1 = (float4*)(out + (size_t)(b + 1) * (NF * 4) + f * 4);
    *o0 = make_float4(m0[0], m0[1], m0[2], m0[3]);
    *o1 = make_float4(m1[0], m1[1], m1[2], m1[3]);
}

// ---------------------------------------------------------------------------
// kernel_launch: transpose/convert + conv. Graph-capturable, allocation-free
// (scratch is a zero-initialized __device__ global; border never written).
// ---------------------------------------------------------------------------
extern "C" void kernel_launch(void* const* d_in, const int* in_sizes, int n_in,
                              void* d_out, int out_size) {
    (void)in_sizes; (void)n_in; (void)out_size;
    const float* X    = (const float*)d_in[0];
    const float* W    = (const float*)d_in[1];
    const float* bias = (const float*)d_in[2];
    const int*   pos  = (const int*)d_in[3];
    float*       out  = (float*)d_out;

    dim3 tb(32, 8);
    dim3 tg(PIX / 32, BATCH / 32);         // (128, 32)
    xt_transpose_kernel<<<tg, tb>>>(X);

    dim3 cg(NF, BATCH / 256);              // (1024, 4)
    filters_conv_kernel<<<cg, 128>>>(W, bias, pos, out);
}

// round 11
// speedup vs baseline: 1.1413x; 1.0499x over previous
#include <cuda_runtime.h>
#include <cuda_fp16.h>
#include <cstdint>
#include <cfloat>

// Problem constants
#define NF    1024
#define BATCH 1024
#define HW    64
#define PIX   (HW * HW)     // 4096
#define PAD   3
#define PW    70            // padded side
#define PPIX  (PW * PW)     // 4900

// 10 MB scratch: zero-PADDED image, fp16, transposed to [padded_pixel][batch].
// __device__ globals are zero-initialized at module load (fp16 zero == 0x0000)
// and the transpose never writes the 3-wide border, so the conv loop needs no
// bounds checks, no border kernel, and no per-load address math.
__device__ __half g_xh[(size_t)PPIX * BATCH];

// ---------------------------------------------------------------------------
// Kernel 1: transpose + fp32->fp16 convert.  X [B, 4096] -> g_xh interior.
// Tile: 32 pixels x 64 batches; stores are full 128B-contiguous half2 rows.
// ---------------------------------------------------------------------------
__global__ void xt_transpose_kernel(const float* __restrict__ X) {
    __shared__ float tile[32][65];          // [pixel_local][batch_local]
    const int p0 = blockIdx.x * 32;         // pixel tile origin
    const int b0 = blockIdx.y * 64;         // batch tile origin
    const int tx = threadIdx.x;             // block (32, 8) = 256 threads
    const int ty = threadIdx.y;

#pragma unroll
    for (int k = 0; k < 64; k += 8)         // coalesced 128B loads
        tile[tx][ty + k] = X[(size_t)(b0 + ty + k) * PIX + (p0 + tx)];
    __syncthreads();

    // 8 warps x 4 pixel-rows each; lane = batch pair -> 128B contiguous STG.
    const int w = ty;                       // warp id 0..7
#pragma unroll
    for (int i = 0; i < 4; i++) {
        const int pl = w * 4 + i;           // pixel local 0..31
        const int p  = p0 + pl;
        const int y  = p >> 6, x = p & 63;
        const __half2 v = __floats2half2_rn(tile[pl][2 * tx],
                                            tile[pl][2 * tx + 1]);
        *(__half2*)(g_xh + (size_t)((y + PAD) * PW + (x + PAD)) * BATCH
                         + b0 + 2 * tx) = v;
    }
}

// ---------------------------------------------------------------------------
// Packed f32x2 helpers (Blackwell packed-FP32 pipe: 2x FFMA throughput)
// ---------------------------------------------------------------------------
__device__ __forceinline__ unsigned long long ffma2(unsigned long long a,
                                                    unsigned long long b,
                                                    unsigned long long c) {
    unsigned long long d;
    asm("fma.rn.f32x2 %0, %1, %2, %3;" : "=l"(d) : "l"(a), "l"(b), "l"(c));
    return d;
}
__device__ __forceinline__ unsigned long long fmul2(unsigned long long a,
                                                    unsigned long long b) {
    unsigned long long d;
    asm("mul.rn.f32x2 %0, %1, %2;" : "=l"(d) : "l"(a), "l"(b));
    return d;
}
__device__ __forceinline__ unsigned long long pack2(float x, float y) {
    unsigned long long r;
    asm("mov.b64 %0, {%1, %2};" : "=l"(r) : "f"(x), "f"(y));
    return r;
}
__device__ __forceinline__ float2 unpack2(unsigned long long v) {
    float2 r;
    asm("mov.b64 {%0, %1}, %2;" : "=f"(r.x), "=f"(r.y) : "l"(v));
    return r;
}
// Non-hoistable broadcast weight load (keeps weights OUT of registers).
__device__ __forceinline__ unsigned long long lds64(uint32_t addr) {
    unsigned long long v;
    asm volatile("ld.shared.b64 %0, [%1];" : "=l"(v) : "r"(addr));
    return v;
}
__device__ __forceinline__ uint32_t smem_u32(const void* p) {
    uint32_t a;
    asm("{ .reg .u64 t; cvta.to.shared.u64 t, %1; cvt.u32.u64 %0, t; }"
        : "=r"(a) : "l"(p));
    return a;
}

// ---------------------------------------------------------------------------
// Kernel 2: per (filter, batch-pair) fused 5x5 conv (only the 6x6 of the 7x7
// outputs the pool reads) + bias + 3x3/3 maxpool.  Each thread owns TWO
// adjacent batches (packed f32x2 math).  Weights live in SMEM (broadcast
// LDS.64, conflict-free); conv rows fold into the running 2x2 max as soon as
// they complete, so at most 30 packed accumulators are live -> ~100 regs ->
// 4-5 resident blocks/SM.
// ---------------------------------------------------------------------------
__global__ void __launch_bounds__(128, 4) filters_conv_kernel(
    const float* __restrict__ W,      // [NF, 25]
    const float* __restrict__ bias,   // [NF]
    const int*   __restrict__ pos,    // [NF, 2]
    float*       __restrict__ out)    // [B, NF*4]
{
    __shared__ unsigned long long wsh[25];   // broadcast-packed (w, w)

    const int f = blockIdx.x;
    const int b = blockIdx.y * 256 + threadIdx.x * 2;  // even -> 4B aligned
    const int pi = __ldg(&pos[2 * f]);
    const int pj = __ldg(&pos[2 * f + 1]);

    if (threadIdx.x < 25) {
        const float w = W[f * 25 + threadIdx.x];
        wsh[threadIdx.x] = pack2(w, w);
    }
    __syncthreads();
    const uint32_t wbase = smem_u32(wsh);

    // Single base pointer; every load below uses a constant byte offset.
    const char* p0 = (const char*)g_xh +
                     ((size_t)(pi * PW + pj) * BATCH + b) * sizeof(__half);

    unsigned long long acc[36];              // <=30 live at any point
    float pm0[4], pm1[4];                    // running 2x2 max per batch
#pragma unroll
    for (int q = 0; q < 4; q++) { pm0[q] = -FLT_MAX; pm1[q] = -FLT_MAX; }

    // Stream the 10 window rows of the zero-padded fp16 image.
#pragma unroll
    for (int r = 0; r < 10; r++) {
        unsigned long long row[10];
#pragma unroll
        for (int c = 0; c < 10; c++) {
            const __half2 h = *(const __half2*)(
                p0 + (size_t)((r * PW + c) * BATCH) * sizeof(__half));
            const float2 fv = __half22float2(h);
            row[c] = pack2(fv.x, fv.y);
        }

        // Row r feeds conv rows oy with ky = r - oy in [0,4].
#pragma unroll
        for (int oy = 0; oy < 6; oy++) {
            const int ky = r - oy;
            if (ky < 0 || ky > 4) continue;       // compile-time pruned
#pragma unroll
            for (int kx = 0; kx < 5; kx++) {
                const unsigned long long w = lds64(wbase + (ky * 5 + kx) * 8);
#pragma unroll
                for (int ox = 0; ox < 6; ox++) {
                    if (ky == 0 && kx == 0)
                        acc[oy * 6 + ox] = fmul2(row[ox], w);
                    else
                        acc[oy * 6 + ox] = ffma2(row[ox + kx], w,
                                                 acc[oy * 6 + ox]);
                }
            }
        }

        // Conv row oy = r-4 is now complete: fold into the pooled max and
        // release its 6 accumulators.
        if (r >= 4) {
            const int oy = r - 4;
            const int py = oy / 3;               // compile-time
#pragma unroll
            for (int px = 0; px < 2; px++) {
#pragma unroll
                for (int dx = 0; dx < 3; dx++) {
                    const float2 v = unpack2(acc[oy * 6 + 3 * px + dx]);
                    pm0[py * 2 + px] = fmaxf(pm0[py * 2 + px], v.x);
                    pm1[py * 2 + px] = fmaxf(pm1[py * 2 + px], v.y);
                }
            }
        }
    }

    // bias (uniform -> add after max) and one float4 store per batch.
    const float bv = __ldg(&bias[f]);
    float4* o0 = (float4*)(out + (size_t)b * (NF * 4) + f * 4);
    float4* o1 = (float4*)(out + (size_t)(b + 1) * (NF * 4) + f * 4);
    *o0 = make_float4(pm0[0] + bv, pm0[1] + bv, pm0[2] + bv, pm0[3] + bv);
    *o1 = make_float4(pm1[0] + bv, pm1[1] + bv, pm1[2] + bv, pm1[3] + bv);
}

// ---------------------------------------------------------------------------
// kernel_launch: transpose/convert + conv. Graph-capturable, allocation-free
// (scratch is a zero-initialized __device__ global; border never written).
// ---------------------------------------------------------------------------
extern "C" void kernel_launch(void* const* d_in, const int* in_sizes, int n_in,
                              void* d_out, int out_size) {
    (void)in_sizes; (void)n_in; (void)out_size;
    const float* X    = (const float*)d_in[0];
    const float* W    = (const float*)d_in[1];
    const float* bias = (const float*)d_in[2];
    const int*   pos  = (const int*)d_in[3];
    float*       out  = (float*)d_out;

    dim3 tb(32, 8);
    dim3 tg(PIX / 32, BATCH / 64);         // (128, 16)
    xt_transpose_kernel<<<tg, tb>>>(X);

    dim3 cg(NF, BATCH / 256);              // (1024, 4)
    filters_conv_kernel<<<cg, 128>>>(W, bias, pos, out);
}